// round 14
// baseline (speedup 1.0000x reference)
#include <cuda_runtime.h>
#include <cuda_fp16.h>
#include <cuda_bf16.h>

// Problem constants
#define BATCH 256
#define VPM   5850
#define NV    (BATCH*VPM)      // 1,497,600 vertices (== 5850*256, exact blocks)
#define NE    (3*NV)           // 4,492,800 edges    (== 17550*256, exact blocks)
#define KDIM  (VPM*10)         // 58,500
#define NOUT  64
#define NEG_SLOPE 0.01f
#define NW8   (NOUT*KDIM/8)    // 468,000 uint4 weight packets

#define VSCALE 8.0f            // fp8 scale for verts (and degree lane)
#define VINV   0.125f
#define XSCALE 32.0f           // fp8 scale for x1
#define XINV   0.03125f

typedef unsigned long long ull;
typedef unsigned int uint;
typedef unsigned short ushort;

// ---------------- scratch (device globals: allocation-free) ----------------
__device__ uint   g_v8[NV];              //  6 MB verts as e4m3x4 (8x,8y,8z,8)
__device__ uint2  g_agg1h[NV];           // 12 MB (8Sx,8Sy,8Sz,8deg) fp16
__device__ uint2  g_x18[NV];             // 12 MB x1 e4m3 x5 (32x) + deg fp16 in y-hi
__device__ uint4  g_agg2h[NV];           // 24 MB agg2 as 8 fp16 (5 used, 32x scale)
__device__ uint4  g_hh4[(size_t)NV*10/8];// 30 MB h fp16 (16B-aligned backing)
__device__ uint4  g_wh4[NW8];            // 7.5 MB fc2_w fp16
__device__ float  g_logits[BATCH*NOUT];  // 64 KB
__device__ int    g_done;                // k5 completion counter (reset in k4)

__device__ __forceinline__ float leaky(float t) {
    return t >= 0.f ? t : NEG_SLOPE * t;
}

// ---------------- f32x2 packed-FMA helpers ----------------------------------
__device__ __forceinline__ void ffma2(ull& d, ull a, ull b) {
    asm("fma.rn.f32x2 %0, %1, %2, %0;" : "+l"(d) : "l"(a), "l"(b));
}
__device__ __forceinline__ ull pack2(float lo, float hi) {
    ull r; asm("mov.b64 %0, {%1,%2};" : "=l"(r) : "f"(lo), "f"(hi)); return r;
}
__device__ __forceinline__ float2 unpack2(ull v) {
    float2 r; asm("mov.b64 {%0,%1}, %2;" : "=f"(r.x), "=f"(r.y) : "l"(v)); return r;
}

// ---------------- fp8 encode/decode -----------------------------------------
__device__ __forceinline__ ushort enc8(float lo, float hi) {
    ushort r;
    asm("cvt.rn.satfinite.e4m3x2.f32 %0, %1, %2;" : "=h"(r) : "f"(hi), "f"(lo));
    return r;
}
__device__ __forceinline__ uint dec8(uint v) {
    uint r;
    asm("cvt.rn.f16x2.e4m3x2 %0, %1;" : "=r"(r) : "h"((ushort)v));
    return r;
}

// ---------------- vectorized global reductions ------------------------------
__device__ __forceinline__ void red_add_v2f16x2(uint2* addr, uint2 v) {
    asm volatile("red.global.add.noftz.v2.f16x2 [%0], {%1,%2};"
                 :: "l"(addr), "r"(v.x), "r"(v.y) : "memory");
}
__device__ __forceinline__ void red_add_v4f16x2(uint4* addr, uint4 v) {
    asm volatile("red.global.add.noftz.v4.f16x2 [%0], {%1,%2,%3,%4};"
                 :: "l"(addr), "r"(v.x), "r"(v.y), "r"(v.z), "r"(v.w) : "memory");
}
__device__ __forceinline__ void red_add_v2f32(float* addr, float2 v) {
    asm volatile("red.global.add.v2.f32 [%0], {%1,%2};"
                 :: "l"(addr), "f"(v.x), "f"(v.y) : "memory");
}

// ---------------- warp mma m16n8k16 fp16 -> fp32 -----------------------------
__device__ __forceinline__ void mma16816(float* c, uint a0, uint a1, uint a2, uint a3,
                                         uint b0, uint b1) {
    asm volatile(
        "mma.sync.aligned.m16n8k16.row.col.f32.f16.f16.f32 "
        "{%0,%1,%2,%3}, {%4,%5,%6,%7}, {%8,%9}, {%0,%1,%2,%3};"
        : "+f"(c[0]), "+f"(c[1]), "+f"(c[2]), "+f"(c[3])
        : "r"(a0), "r"(a1), "r"(a2), "r"(a3), "r"(b0), "r"(b1));
}

// ---------------- K0: verts -> e4m3x4; zero agg1h ---------------------------
__global__ void k0_pad(const float* __restrict__ verts) {
    int v = blockIdx.x * blockDim.x + threadIdx.x;
    float vx = verts[3*v+0], vy = verts[3*v+1], vz = verts[3*v+2];
    uint lo = enc8(VSCALE*vx, VSCALE*vy);
    uint hi = enc8(VSCALE*vz, VSCALE);
    g_v8[v] = lo | (hi << 16);
    g_agg1h[v] = make_uint2(0u, 0u);
}

// ---------------- K1: edge pass 1; zero agg2h; fc2_w -> fp16 ----------------
// the LTS-bound edge kernel issues at ~5%; coalesced side-work rides free.
__global__ void k1_edge_agg1(const int* __restrict__ edges, const float* __restrict__ w) {
    int e = blockIdx.x * blockDim.x + threadIdx.x;
    if (e < NV) g_agg2h[e] = make_uint4(0u, 0u, 0u, 0u);   // fold memset
    if (e < NW8) {                                         // fold w fp32->fp16
        float4 a = __ldg(((const float4*)w) + 2*e);
        float4 b = __ldg(((const float4*)w) + 2*e + 1);
        __half2 h0 = __floats2half2_rn(a.x, a.y);
        __half2 h1 = __floats2half2_rn(a.z, a.w);
        __half2 h2 = __floats2half2_rn(b.x, b.y);
        __half2 h3 = __floats2half2_rn(b.z, b.w);
        uint4 o;
        o.x = *(uint*)&h0; o.y = *(uint*)&h1; o.z = *(uint*)&h2; o.w = *(uint*)&h3;
        g_wh4[e] = o;
    }
    int2 ep = __ldg(((const int2*)edges) + e);
    uint pi = __ldg(&g_v8[ep.x]);
    uint pj = __ldg(&g_v8[ep.y]);
    uint2 vi = make_uint2(dec8(pi & 0xffffu), dec8(pi >> 16));
    uint2 vj = make_uint2(dec8(pj & 0xffffu), dec8(pj >> 16));
    red_add_v2f16x2(&g_agg1h[ep.x], vj);
    red_add_v2f16x2(&g_agg1h[ep.y], vi);
}

// ---------------- K2: vertex pass 1 — x1 = leaky(gc1); store fp8+deg -------
__global__ void k2_vert1(const float* __restrict__ w0a, const float* __restrict__ b0a,
                         const float* __restrict__ w1a, const float* __restrict__ b1a) {
    int v = blockIdx.x * blockDim.x + threadIdx.x;
    uint pv = g_v8[v];
    uint q0 = dec8(pv & 0xffffu), q1 = dec8(pv >> 16);
    float2 p01 = __half22float2(*reinterpret_cast<__half2*>(&q0));
    float2 p2_ = __half22float2(*reinterpret_cast<__half2*>(&q1));
    float p[3] = {p01.x * VINV, p01.y * VINV, p2_.x * VINV};
    uint2 ar = g_agg1h[v];
    float2 a01 = __half22float2(*reinterpret_cast<__half2*>(&ar.x));
    float2 a2d = __half22float2(*reinterpret_cast<__half2*>(&ar.y));
    float a[3] = {a01.x * VINV, a01.y * VINV, a2d.x * VINV};
    float dg = a2d.y * VINV;   // degree (exact: 8n in fp16, n<=2048)
    float x[5];
#pragma unroll
    for (int k = 0; k < 5; k++) {
        float t = __ldg(b0a + k) + dg * __ldg(b1a + k);
#pragma unroll
        for (int c = 0; c < 3; c++)
            t += __ldg(w0a + k*3 + c) * p[c] + __ldg(w1a + k*3 + c) * a[c];
        x[k] = leaky(t);
    }
    __half dgh = __float2half_rn(dg);
    uint2 o8;
    o8.x = (uint)enc8(XSCALE*x[0], XSCALE*x[1]) | ((uint)enc8(XSCALE*x[2], XSCALE*x[3]) << 16);
    o8.y = (uint)enc8(XSCALE*x[4], 0.f) | ((uint)*(ushort*)&dgh << 16);
    g_x18[v] = o8;
}

// ---------------- K3: edge pass 2 — fp8 gather (8B) + fp16 red (16B) -------
__global__ void k3_edge_agg2(const int* __restrict__ edges) {
    int e = blockIdx.x * blockDim.x + threadIdx.x;
    int2 ep = __ldg(((const int2*)edges) + e);
    uint2 pj = __ldg(&g_x18[ep.y]);
    uint2 pi = __ldg(&g_x18[ep.x]);
    uint4 xj = make_uint4(dec8(pj.x & 0xffffu), dec8(pj.x >> 16), dec8(pj.y & 0xffffu), 0u);
    uint4 xi = make_uint4(dec8(pi.x & 0xffffu), dec8(pi.x >> 16), dec8(pi.y & 0xffffu), 0u);
    red_add_v4f16x2(&g_agg2h[ep.x], xj);
    red_add_v4f16x2(&g_agg2h[ep.y], xi);
}

// ---------------- K4: fused gc2 + leaky + fc1 + leaky (f32x2) --------------
__global__ void k4_vert2_fc1(const float* __restrict__ w0b, const float* __restrict__ b0b,
                             const float* __restrict__ w1b, const float* __restrict__ b1b,
                             const float* __restrict__ fc1_w, const float* __restrict__ fc1_b) {
    __shared__ float2 sAB[100];   // (w0b*XINV, w1b*XINV) at k*5+c
    __shared__ float2 sF[100];    // (fc1_w[m][2q], fc1_w[m][2q+1]) at m*10+q
    __shared__ float  sb0[20], sb1[20], sfb[10];
    __shared__ __align__(16) uint s_h[256*5]; // staging for coalesced writeback
    int t = threadIdx.x;
    if (t < 100) {
        sAB[t] = make_float2(w0b[t]*XINV, w1b[t]*XINV);
        sF[t]  = ((const float2*)fc1_w)[t];
    }
    if (t < 20) { sb0[t] = b0b[t]; sb1[t] = b1b[t]; }
    if (t < 10) { sfb[t] = fc1_b[t]; }
    __syncthreads();

    int v = blockIdx.x * blockDim.x + t;
    if (v < BATCH*NOUT) g_logits[v] = 0.f;   // fold memset (k5 runs after)
    if (v == 0) g_done = 0;                  // reset k5 completion counter

    uint2 xr = g_x18[v];
    uint4 ar = g_agg2h[v];
    uint d0 = dec8(xr.x & 0xffffu), d1 = dec8(xr.x >> 16), d2 = dec8(xr.y & 0xffffu);
    float2 x01 = __half22float2(*reinterpret_cast<__half2*>(&d0));
    float2 x23 = __half22float2(*reinterpret_cast<__half2*>(&d1));
    float2 x4_ = __half22float2(*reinterpret_cast<__half2*>(&d2));
    float2 a01 = __half22float2(*reinterpret_cast<__half2*>(&ar.x));
    float2 a23 = __half22float2(*reinterpret_cast<__half2*>(&ar.y));
    float2 a4_ = __half22float2(*reinterpret_cast<__half2*>(&ar.z));
    float xv[5] = {x01.x, x01.y, x23.x, x23.y, x4_.x};     // 32x domain
    float av[5] = {a01.x, a01.y, a23.x, a23.y, a4_.x};     // 32x domain
    ushort dgu = (ushort)(xr.y >> 16);
    float dg = __half2float(*(const __half*)&dgu);

    ull xa[5];
#pragma unroll
    for (int c = 0; c < 5; c++) xa[c] = pack2(xv[c], av[c]);

    float x2[20];
#pragma unroll
    for (int k = 0; k < 20; k++) {
        ull acc = pack2(fmaf(dg, sb1[k], sb0[k]), 0.f);
#pragma unroll
        for (int c = 0; c < 5; c++)
            ffma2(acc, xa[c], *(const ull*)&sAB[k*5 + c]);
        float2 r = unpack2(acc);
        x2[k] = leaky(r.x + r.y);
    }

    ull x2p[10];
#pragma unroll
    for (int q = 0; q < 10; q++) x2p[q] = pack2(x2[2*q], x2[2*q+1]);

#pragma unroll
    for (int m = 0; m < 10; m += 2) {
        ull acc0 = pack2(sfb[m],   0.f);
        ull acc1 = pack2(sfb[m+1], 0.f);
#pragma unroll
        for (int q = 0; q < 10; q++) {
            ffma2(acc0, x2p[q], *(const ull*)&sF[m*10 + q]);
            ffma2(acc1, x2p[q], *(const ull*)&sF[(m+1)*10 + q]);
        }
        float2 r0 = unpack2(acc0);
        float2 r1 = unpack2(acc1);
        __half2 hp = __floats2half2_rn(leaky(r0.x + r0.y), leaky(r1.x + r1.y));
        s_h[t*5 + (m >> 1)] = *(uint*)&hp;   // stride-5: bank-conflict-free
    }
    __syncthreads();
    // coalesced writeback: 1280 uints = 320 uint4 per block (5120B stride)
    uint4* gout = g_hh4 + (size_t)blockIdx.x * 320;
    const uint4* sin = (const uint4*)s_h;
    gout[t] = sin[t];
    if (t < 64) gout[256 + t] = sin[256 + t];
}

// ---------------- K5: fc2 GEMM (tensor cores) + fused bias/softmax ---------
#define K5_CHUNK  960
#define K5_GRIDX  61    // 61*960 = 58560 >= 58500
#define K5_NBLK   (K5_GRIDX*2)
#define K5_KT     32    // halves per stage
#define SROW      40    // smem row stride in halves (conflict-free, 16B-aligned)

__global__ void k5_fc2(const float* __restrict__ fc2_b, float* __restrict__ out) {
    __shared__ __align__(16) __half sA[128*SROW];
    __shared__ __align__(16) __half sB[64*SROW];
    int tid = threadIdx.x;
    int warp = tid >> 5, lane = tid & 31;
    int g = lane >> 2, t4 = lane & 3;
    int mbase = blockIdx.y * 128;
    int kbeg = blockIdx.x * K5_CHUNK;
    int klen = KDIM - kbeg; if (klen > K5_CHUNK) klen = K5_CHUNK;
    int nstages = (klen + K5_KT - 1) / K5_KT;

    const __half* hbase = (const __half*)g_hh4;
    const __half* wbase = (const __half*)g_wh4;

    float c[8][4];
#pragma unroll
    for (int nt = 0; nt < 8; nt++)
#pragma unroll
        for (int i = 0; i < 4; i++) c[nt][i] = 0.f;

    uint2 rA[4], rB[2];
    auto load_stage = [&](int s) {
        int k0 = kbeg + s * K5_KT;
#pragma unroll
        for (int i = 0; i < 4; i++) {
            int idx = tid + i * 256;           // 0..1023
            int row = idx >> 3, c2 = idx & 7;  // col = c2*4 halves
            int k = k0 + c2 * 4;
            rA[i] = (k < KDIM)
                ? __ldg((const uint2*)(hbase + (size_t)(mbase + row) * KDIM + k))
                : make_uint2(0u, 0u);
        }
#pragma unroll
        for (int i = 0; i < 2; i++) {
            int idx = tid + i * 256;           // 0..511
            int row = idx >> 3, c2 = idx & 7;
            int k = k0 + c2 * 4;
            rB[i] = (k < KDIM)
                ? __ldg((const uint2*)(wbase + (size_t)row * KDIM + k))
                : make_uint2(0u, 0u);
        }
    };

    load_stage(0);
    for (int s = 0; s < nstages; s++) {
#pragma unroll
        for (int i = 0; i < 4; i++) {
            int idx = tid + i * 256;
            int row = idx >> 3, c2 = idx & 7;
            *(uint2*)&sA[row * SROW + c2 * 4] = rA[i];
        }
#pragma unroll
        for (int i = 0; i < 2; i++) {
            int idx = tid + i * 256;
            int row = idx >> 3, c2 = idx & 7;
            *(uint2*)&sB[row * SROW + c2 * 4] = rB[i];
        }
        __syncthreads();
        if (s + 1 < nstages) load_stage(s + 1);

        int wm = warp * 16;
#pragma unroll
        for (int kk = 0; kk < 2; kk++) {
            int kc = kk * 16;
            uint a0 = *(const uint*)&sA[(wm + g    ) * SROW + kc     + 2*t4];
            uint a1 = *(const uint*)&sA[(wm + g + 8) * SROW + kc     + 2*t4];
            uint a2 = *(const uint*)&sA[(wm + g    ) * SROW + kc + 8 + 2*t4];
            uint a3 = *(const uint*)&sA[(wm + g + 8) * SROW + kc + 8 + 2*t4];
#pragma unroll
            for (int nt = 0; nt < 8; nt++) {
                uint b0 = *(const uint*)&sB[(nt*8 + g) * SROW + kc     + 2*t4];
                uint b1 = *(const uint*)&sB[(nt*8 + g) * SROW + kc + 8 + 2*t4];
                mma16816(c[nt], a0, a1, a2, a3, b0, b1);
            }
        }
        __syncthreads();
    }

    int row0 = mbase + warp * 16 + g;
#pragma unroll
    for (int nt = 0; nt < 8; nt++) {
        int col = nt * 8 + 2 * t4;
        red_add_v2f32(&g_logits[row0 * NOUT + col],       make_float2(c[nt][0], c[nt][1]));
        red_add_v2f32(&g_logits[(row0 + 8) * NOUT + col], make_float2(c[nt][2], c[nt][3]));
    }

    // ---- completion-counter fused epilogue: last block does softmax ----
    __threadfence();
    __shared__ int s_ticket;
    if (tid == 0) s_ticket = atomicAdd(&g_done, 1);
    __syncthreads();
    if (s_ticket != K5_NBLK - 1) return;

    // last block: bias + softmax over 256 rows of 64 (8 warps x 32 rows)
    float2 bb = *(const float2*)&fc2_b[lane * 2];
    for (int i = 0; i < 32; i++) {
        int row = warp * 32 + i;
        float2 lv = __ldcg((const float2*)&g_logits[row * NOUT + lane * 2]);
        float a0 = lv.x + bb.x, a1 = lv.y + bb.y;
        float mx = fmaxf(a0, a1);
#pragma unroll
        for (int off = 16; off > 0; off >>= 1)
            mx = fmaxf(mx, __shfl_xor_sync(0xffffffffu, mx, off));
        float e0 = __expf(a0 - mx), e1 = __expf(a1 - mx);
        float sm = e0 + e1;
#pragma unroll
        for (int off = 16; off > 0; off >>= 1)
            sm += __shfl_xor_sync(0xffffffffu, sm, off);
        float inv = __frcp_rn(sm);
        *(float2*)&out[row * NOUT + lane * 2] = make_float2(e0 * inv, e1 * inv);
    }
}

// ---------------- launch ----------------------------------------------------
extern "C" void kernel_launch(void* const* d_in, const int* in_sizes, int n_in,
                              void* d_out, int out_size) {
    const float* verts = (const float*)d_in[0];
    const int*   edges = (const int*)  d_in[1];   // int32
    const float* w0a = (const float*)d_in[2];
    const float* b0a = (const float*)d_in[3];
    const float* w1a = (const float*)d_in[4];
    const float* b1a = (const float*)d_in[5];
    const float* w0b = (const float*)d_in[6];
    const float* b0b = (const float*)d_in[7];
    const float* w1b = (const float*)d_in[8];
    const float* b1b = (const float*)d_in[9];
    const float* fc1_w = (const float*)d_in[10];
    const float* fc1_b = (const float*)d_in[11];
    const float* fc2_w = (const float*)d_in[12];
    const float* fc2_b = (const float*)d_in[13];
    float* out = (float*)d_out;

    const int TB = 256;
    const int eblocks = NE / TB;   // exact
    const int vblocks = NV / TB;   // exact

    k0_pad      <<<vblocks, TB>>>(verts);
    k1_edge_agg1<<<eblocks, TB>>>(edges, fc2_w);
    k2_vert1    <<<vblocks, TB>>>(w0a, b0a, w1a, b1a);
    k3_edge_agg2<<<eblocks, TB>>>(edges);
    k4_vert2_fc1<<<vblocks, TB>>>(w0b, b0b, w1b, b1b, fc1_w, fc1_b);
    dim3 g5(K5_GRIDX, 2);
    k5_fc2      <<<g5, 256>>>(fc2_b, out);
}

// round 15
// speedup vs baseline: 1.0698x; 1.0698x over previous
#include <cuda_runtime.h>
#include <cuda_fp16.h>
#include <cuda_bf16.h>

// Problem constants
#define BATCH 256
#define VPM   5850
#define NV    (BATCH*VPM)      // 1,497,600 vertices
#define NE    (3*NV)           // 4,492,800 edges
#define KDIM  (VPM*10)         // 58,500
#define NOUT  64
#define NEG_SLOPE 0.01f
#define NW8   (NOUT*KDIM/8)    // 468,000 uint4 weight packets

#define VSCALE 8.0f            // fp8 scale for verts (and degree lane)
#define VINV   0.125f
#define XSCALE 32.0f           // fp8 scale for x1
#define XINV   0.03125f

typedef unsigned long long ull;
typedef unsigned int uint;
typedef unsigned short ushort;

// ---------------- scratch (device globals: allocation-free) ----------------
__device__ uint   g_v8[NV];              //  6 MB verts as e4m3x4 (8x,8y,8z,8)
__device__ uint2  g_agg1h[NV];           // 12 MB (8Sx,8Sy,8Sz,8deg) fp16
__device__ uint2  g_x18[NV];             // 12 MB x1 e4m3 x5 (32x) + deg fp16 in y-hi
__device__ uint4  g_agg2h[NV];           // 24 MB agg2 as 8 fp16 (5 used, 32x scale)
__device__ uint4  g_hh4[(size_t)NV*10/8];// 30 MB h fp16 (16B-aligned backing)
__device__ uint4  g_wh4[NW8];            // 7.5 MB fc2_w fp16
__device__ float  g_logits[BATCH*NOUT];  // 64 KB

__device__ __forceinline__ float leaky(float t) {
    return t >= 0.f ? t : NEG_SLOPE * t;
}

// ---------------- f32x2 packed-FMA helpers ----------------------------------
__device__ __forceinline__ void ffma2(ull& d, ull a, ull b) {
    asm("fma.rn.f32x2 %0, %1, %2, %0;" : "+l"(d) : "l"(a), "l"(b));
}
__device__ __forceinline__ ull pack2(float lo, float hi) {
    ull r; asm("mov.b64 %0, {%1,%2};" : "=l"(r) : "f"(lo), "f"(hi)); return r;
}
__device__ __forceinline__ float2 unpack2(ull v) {
    float2 r; asm("mov.b64 {%0,%1}, %2;" : "=f"(r.x), "=f"(r.y) : "l"(v)); return r;
}

// ---------------- fp8 encode/decode -----------------------------------------
__device__ __forceinline__ ushort enc8(float lo, float hi) {
    ushort r;
    asm("cvt.rn.satfinite.e4m3x2.f32 %0, %1, %2;" : "=h"(r) : "f"(hi), "f"(lo));
    return r;
}
__device__ __forceinline__ uint dec8(uint v) {
    uint r;
    asm("cvt.rn.f16x2.e4m3x2 %0, %1;" : "=r"(r) : "h"((ushort)v));
    return r;
}

// ---------------- vectorized global reductions ------------------------------
__device__ __forceinline__ void red_add_v2f16x2(uint2* addr, uint2 v) {
    asm volatile("red.global.add.noftz.v2.f16x2 [%0], {%1,%2};"
                 :: "l"(addr), "r"(v.x), "r"(v.y) : "memory");
}
__device__ __forceinline__ void red_add_v4f16x2(uint4* addr, uint4 v) {
    asm volatile("red.global.add.noftz.v4.f16x2 [%0], {%1,%2,%3,%4};"
                 :: "l"(addr), "r"(v.x), "r"(v.y), "r"(v.z), "r"(v.w) : "memory");
}
__device__ __forceinline__ void red_add_v2f32(float* addr, float2 v) {
    asm volatile("red.global.add.v2.f32 [%0], {%1,%2};"
                 :: "l"(addr), "f"(v.x), "f"(v.y) : "memory");
}

// ---------------- warp mma m16n8k16 fp16 -> fp32 -----------------------------
__device__ __forceinline__ void mma16816(float* c, uint a0, uint a1, uint a2, uint a3,
                                         uint b0, uint b1) {
    asm volatile(
        "mma.sync.aligned.m16n8k16.row.col.f32.f16.f16.f32 "
        "{%0,%1,%2,%3}, {%4,%5,%6,%7}, {%8,%9}, {%0,%1,%2,%3};"
        : "+f"(c[0]), "+f"(c[1]), "+f"(c[2]), "+f"(c[3])
        : "r"(a0), "r"(a1), "r"(a2), "r"(a3), "r"(b0), "r"(b1));
}

// ---------------- K0: 4 verts/thread -> e4m3x4; zero agg1h; w -> fp16 -------
// grid 2925 x 128: 374,400 threads, 4 vertices each (exact)
__global__ void k0_pad(const float* __restrict__ verts, const float* __restrict__ w) {
    int t = blockIdx.x * blockDim.x + threadIdx.x;   // 0 .. NV/4-1
    const float4* vp = ((const float4*)verts) + (size_t)t * 3;
    float4 f0 = __ldg(vp + 0);
    float4 f1 = __ldg(vp + 1);
    float4 f2 = __ldg(vp + 2);
    uint4 o;
    o.x = (uint)enc8(VSCALE*f0.x, VSCALE*f0.y) | ((uint)enc8(VSCALE*f0.z, VSCALE) << 16);
    o.y = (uint)enc8(VSCALE*f0.w, VSCALE*f1.x) | ((uint)enc8(VSCALE*f1.y, VSCALE) << 16);
    o.z = (uint)enc8(VSCALE*f1.z, VSCALE*f1.w) | ((uint)enc8(VSCALE*f2.x, VSCALE) << 16);
    o.w = (uint)enc8(VSCALE*f2.y, VSCALE*f2.z) | ((uint)enc8(VSCALE*f2.w, VSCALE) << 16);
    *(uint4*)&g_v8[t * 4] = o;
    uint4 z = make_uint4(0u, 0u, 0u, 0u);
    ((uint4*)g_agg1h)[t*2 + 0] = z;
    ((uint4*)g_agg1h)[t*2 + 1] = z;
    // fc2_w fp32 -> fp16: packets t and t + NV/4
#pragma unroll
    for (int rep = 0; rep < 2; rep++) {
        int p = t + rep * (NV/4);
        if (p < NW8) {
            float4 a = __ldg(((const float4*)w) + 2*p);
            float4 b = __ldg(((const float4*)w) + 2*p + 1);
            __half2 h0 = __floats2half2_rn(a.x, a.y);
            __half2 h1 = __floats2half2_rn(a.z, a.w);
            __half2 h2 = __floats2half2_rn(b.x, b.y);
            __half2 h3 = __floats2half2_rn(b.z, b.w);
            uint4 ow;
            ow.x = *(uint*)&h0; ow.y = *(uint*)&h1; ow.z = *(uint*)&h2; ow.w = *(uint*)&h3;
            g_wh4[p] = ow;
        }
    }
}

// ---------------- K1: edge pass 1 (4B gather + 8B red); zero agg2h ---------
__global__ void k1_edge_agg1(const int* __restrict__ edges) {
    int e = blockIdx.x * blockDim.x + threadIdx.x;
    if (e < NV) g_agg2h[e] = make_uint4(0u, 0u, 0u, 0u);   // fold memset
    int2 ep = __ldg(((const int2*)edges) + e);
    uint pi = __ldg(&g_v8[ep.x]);
    uint pj = __ldg(&g_v8[ep.y]);
    uint2 vi = make_uint2(dec8(pi & 0xffffu), dec8(pi >> 16));
    uint2 vj = make_uint2(dec8(pj & 0xffffu), dec8(pj >> 16));
    red_add_v2f16x2(&g_agg1h[ep.x], vj);
    red_add_v2f16x2(&g_agg1h[ep.y], vi);
}

// ---------------- K2: 2 verts/thread — x1 = leaky(gc1); store fp8+deg ------
// grid 2925 x 256: 748,800 threads, 2 vertices each (exact)
__global__ void k2_vert1(const float* __restrict__ w0a, const float* __restrict__ b0a,
                         const float* __restrict__ w1a, const float* __restrict__ b1a) {
    int t = blockIdx.x * blockDim.x + threadIdx.x;
    int v = t * 2;
    uint2 pv  = *(const uint2*)&g_v8[v];          // 2 vertices, 8B aligned
    uint4 ar  = *(const uint4*)&g_agg1h[v];       // 2 aggregates, 16B aligned

    // broadcast weights once (L1/const-hot), reused for both vertices
    float w0[15], w1[15], b0[5], b1[5];
#pragma unroll
    for (int i = 0; i < 15; i++) { w0[i] = __ldg(w0a + i); w1[i] = __ldg(w1a + i); }
#pragma unroll
    for (int i = 0; i < 5; i++)  { b0[i] = __ldg(b0a + i); b1[i] = __ldg(b1a + i); }

    uint pvv[2] = {pv.x, pv.y};
    uint arr[2][2] = {{ar.x, ar.y}, {ar.z, ar.w}};
    uint2 o8[2];
#pragma unroll
    for (int s = 0; s < 2; s++) {
        uint q0 = dec8(pvv[s] & 0xffffu), q1 = dec8(pvv[s] >> 16);
        float2 p01 = __half22float2(*reinterpret_cast<__half2*>(&q0));
        float2 p2_ = __half22float2(*reinterpret_cast<__half2*>(&q1));
        float p[3] = {p01.x * VINV, p01.y * VINV, p2_.x * VINV};
        uint a0 = arr[s][0], a1u = arr[s][1];
        float2 a01 = __half22float2(*reinterpret_cast<__half2*>(&a0));
        float2 a2d = __half22float2(*reinterpret_cast<__half2*>(&a1u));
        float a[3] = {a01.x * VINV, a01.y * VINV, a2d.x * VINV};
        float dg = a2d.y * VINV;   // degree (exact: 8n in fp16, n<=2048)
        float x[5];
#pragma unroll
        for (int k = 0; k < 5; k++) {
            float tt = b0[k] + dg * b1[k];
#pragma unroll
            for (int c = 0; c < 3; c++)
                tt += w0[k*3 + c] * p[c] + w1[k*3 + c] * a[c];
            x[k] = leaky(tt);
        }
        __half dgh = __float2half_rn(dg);
        o8[s].x = (uint)enc8(XSCALE*x[0], XSCALE*x[1]) | ((uint)enc8(XSCALE*x[2], XSCALE*x[3]) << 16);
        o8[s].y = (uint)enc8(XSCALE*x[4], 0.f) | ((uint)*(ushort*)&dgh << 16);
    }
    uint4 out4 = make_uint4(o8[0].x, o8[0].y, o8[1].x, o8[1].y);
    *(uint4*)&g_x18[v] = out4;   // 16B aligned (v even)
}

// ---------------- K3: edge pass 2 — fp8 gather (8B) + fp16 red (16B) -------
__global__ void k3_edge_agg2(const int* __restrict__ edges) {
    int e = blockIdx.x * blockDim.x + threadIdx.x;
    int2 ep = __ldg(((const int2*)edges) + e);
    uint2 pj = __ldg(&g_x18[ep.y]);
    uint2 pi = __ldg(&g_x18[ep.x]);
    uint4 xj = make_uint4(dec8(pj.x & 0xffffu), dec8(pj.x >> 16), dec8(pj.y & 0xffffu), 0u);
    uint4 xi = make_uint4(dec8(pi.x & 0xffffu), dec8(pi.x >> 16), dec8(pi.y & 0xffffu), 0u);
    red_add_v4f16x2(&g_agg2h[ep.x], xj);
    red_add_v4f16x2(&g_agg2h[ep.y], xi);
}

// ---------------- K4: fused gc2 + leaky + fc1 + leaky (f32x2) --------------
__global__ void k4_vert2_fc1(const float* __restrict__ w0b, const float* __restrict__ b0b,
                             const float* __restrict__ w1b, const float* __restrict__ b1b,
                             const float* __restrict__ fc1_w, const float* __restrict__ fc1_b) {
    __shared__ float2 sAB[100];   // (w0b*XINV, w1b*XINV) at k*5+c
    __shared__ float2 sF[100];    // (fc1_w[m][2q], fc1_w[m][2q+1]) at m*10+q
    __shared__ float  sb0[20], sb1[20], sfb[10];
    __shared__ __align__(16) uint s_h[256*5]; // staging for coalesced writeback
    int t = threadIdx.x;
    if (t < 100) {
        sAB[t] = make_float2(w0b[t]*XINV, w1b[t]*XINV);
        sF[t]  = ((const float2*)fc1_w)[t];
    }
    if (t < 20) { sb0[t] = b0b[t]; sb1[t] = b1b[t]; }
    if (t < 10) { sfb[t] = fc1_b[t]; }
    __syncthreads();

    int v = blockIdx.x * blockDim.x + t;
    if (v < BATCH*NOUT) g_logits[v] = 0.f;   // fold memset (k5 runs after)

    uint2 xr = g_x18[v];
    uint4 ar = g_agg2h[v];
    uint d0 = dec8(xr.x & 0xffffu), d1 = dec8(xr.x >> 16), d2 = dec8(xr.y & 0xffffu);
    float2 x01 = __half22float2(*reinterpret_cast<__half2*>(&d0));
    float2 x23 = __half22float2(*reinterpret_cast<__half2*>(&d1));
    float2 x4_ = __half22float2(*reinterpret_cast<__half2*>(&d2));
    float2 a01 = __half22float2(*reinterpret_cast<__half2*>(&ar.x));
    float2 a23 = __half22float2(*reinterpret_cast<__half2*>(&ar.y));
    float2 a4_ = __half22float2(*reinterpret_cast<__half2*>(&ar.z));
    float xv[5] = {x01.x, x01.y, x23.x, x23.y, x4_.x};     // 32x domain
    float av[5] = {a01.x, a01.y, a23.x, a23.y, a4_.x};     // 32x domain
    ushort dgu = (ushort)(xr.y >> 16);
    float dg = __half2float(*(const __half*)&dgu);

    ull xa[5];
#pragma unroll
    for (int c = 0; c < 5; c++) xa[c] = pack2(xv[c], av[c]);

    float x2[20];
#pragma unroll
    for (int k = 0; k < 20; k++) {
        ull acc = pack2(fmaf(dg, sb1[k], sb0[k]), 0.f);
#pragma unroll
        for (int c = 0; c < 5; c++)
            ffma2(acc, xa[c], *(const ull*)&sAB[k*5 + c]);
        float2 r = unpack2(acc);
        x2[k] = leaky(r.x + r.y);
    }

    ull x2p[10];
#pragma unroll
    for (int q = 0; q < 10; q++) x2p[q] = pack2(x2[2*q], x2[2*q+1]);

#pragma unroll
    for (int m = 0; m < 10; m += 2) {
        ull acc0 = pack2(sfb[m],   0.f);
        ull acc1 = pack2(sfb[m+1], 0.f);
#pragma unroll
        for (int q = 0; q < 10; q++) {
            ffma2(acc0, x2p[q], *(const ull*)&sF[m*10 + q]);
            ffma2(acc1, x2p[q], *(const ull*)&sF[(m+1)*10 + q]);
        }
        float2 r0 = unpack2(acc0);
        float2 r1 = unpack2(acc1);
        __half2 hp = __floats2half2_rn(leaky(r0.x + r0.y), leaky(r1.x + r1.y));
        s_h[t*5 + (m >> 1)] = *(uint*)&hp;   // stride-5: bank-conflict-free
    }
    __syncthreads();
    // coalesced writeback: 1280 uints = 320 uint4 per block (5120B stride)
    uint4* gout = g_hh4 + (size_t)blockIdx.x * 320;
    const uint4* sin = (const uint4*)s_h;
    gout[t] = sin[t];
    if (t < 64) gout[256 + t] = sin[256 + t];
}

// ---------------- K5: fc2 GEMM on tensor cores (m16n8k16) ------------------
#define K5_CHUNK  960
#define K5_GRIDX  61    // 61*960 = 58560 >= 58500
#define K5_KT     32    // halves per stage
#define SROW      40    // smem row stride in halves (conflict-free, 16B-aligned)

__global__ void k5_fc2() {
    __shared__ __align__(16) __half sA[128*SROW];
    __shared__ __align__(16) __half sB[64*SROW];
    int tid = threadIdx.x;
    int warp = tid >> 5, lane = tid & 31;
    int g = lane >> 2, t4 = lane & 3;
    int mbase = blockIdx.y * 128;
    int kbeg = blockIdx.x * K5_CHUNK;
    int klen = KDIM - kbeg; if (klen > K5_CHUNK) klen = K5_CHUNK;
    int nstages = (klen + K5_KT - 1) / K5_KT;

    const __half* hbase = (const __half*)g_hh4;
    const __half* wbase = (const __half*)g_wh4;

    float c[8][4];
#pragma unroll
    for (int nt = 0; nt < 8; nt++)
#pragma unroll
        for (int i = 0; i < 4; i++) c[nt][i] = 0.f;

    uint2 rA[4], rB[2];
    auto load_stage = [&](int s) {
        int k0 = kbeg + s * K5_KT;
#pragma unroll
        for (int i = 0; i < 4; i++) {
            int idx = tid + i * 256;           // 0..1023
            int row = idx >> 3, c2 = idx & 7;  // col = c2*4 halves
            int k = k0 + c2 * 4;
            rA[i] = (k < KDIM)
                ? __ldg((const uint2*)(hbase + (size_t)(mbase + row) * KDIM + k))
                : make_uint2(0u, 0u);
        }
#pragma unroll
        for (int i = 0; i < 2; i++) {
            int idx = tid + i * 256;           // 0..511
            int row = idx >> 3, c2 = idx & 7;
            int k = k0 + c2 * 4;
            rB[i] = (k < KDIM)
                ? __ldg((const uint2*)(wbase + (size_t)row * KDIM + k))
                : make_uint2(0u, 0u);
        }
    };

    load_stage(0);
    for (int s = 0; s < nstages; s++) {
#pragma unroll
        for (int i = 0; i < 4; i++) {
            int idx = tid + i * 256;
            int row = idx >> 3, c2 = idx & 7;
            *(uint2*)&sA[row * SROW + c2 * 4] = rA[i];
        }
#pragma unroll
        for (int i = 0; i < 2; i++) {
            int idx = tid + i * 256;
            int row = idx >> 3, c2 = idx & 7;
            *(uint2*)&sB[row * SROW + c2 * 4] = rB[i];
        }
        __syncthreads();
        if (s + 1 < nstages) load_stage(s + 1);

        int wm = warp * 16;
#pragma unroll
        for (int kk = 0; kk < 2; kk++) {
            int kc = kk * 16;
            uint a0 = *(const uint*)&sA[(wm + g    ) * SROW + kc     + 2*t4];
            uint a1 = *(const uint*)&sA[(wm + g + 8) * SROW + kc     + 2*t4];
            uint a2 = *(const uint*)&sA[(wm + g    ) * SROW + kc + 8 + 2*t4];
            uint a3 = *(const uint*)&sA[(wm + g + 8) * SROW + kc + 8 + 2*t4];
#pragma unroll
            for (int nt = 0; nt < 8; nt++) {
                uint b0 = *(const uint*)&sB[(nt*8 + g) * SROW + kc     + 2*t4];
                uint b1 = *(const uint*)&sB[(nt*8 + g) * SROW + kc + 8 + 2*t4];
                mma16816(c[nt], a0, a1, a2, a3, b0, b1);
            }
        }
        __syncthreads();
    }

    int row0 = mbase + warp * 16 + g;
#pragma unroll
    for (int nt = 0; nt < 8; nt++) {
        int col = nt * 8 + 2 * t4;
        red_add_v2f32(&g_logits[row0 * NOUT + col],       make_float2(c[nt][0], c[nt][1]));
        red_add_v2f32(&g_logits[(row0 + 8) * NOUT + col], make_float2(c[nt][2], c[nt][3]));
    }
}

// ---------------- K6: bias + softmax over 64 -------------------------------
__global__ void k6_softmax(const float* __restrict__ fc2_b, float* __restrict__ out) {
    int b = blockIdx.x;
    int t = threadIdx.x;  // 64
    __shared__ float s[64];
    float x = g_logits[b*NOUT + t] + fc2_b[t];
    s[t] = x; __syncthreads();
#pragma unroll
    for (int off = 32; off > 0; off >>= 1) {
        if (t < off) s[t] = fmaxf(s[t], s[t + off]);
        __syncthreads();
    }
    float m = s[0];
    __syncthreads();
    float e = expf(x - m);
    s[t] = e; __syncthreads();
#pragma unroll
    for (int off = 32; off > 0; off >>= 1) {
        if (t < off) s[t] = s[t] + s[t + off];
        __syncthreads();
    }
    float sum = s[0];
    out[b*NOUT + t] = e / sum;
}

// ---------------- launch ----------------------------------------------------
extern "C" void kernel_launch(void* const* d_in, const int* in_sizes, int n_in,
                              void* d_out, int out_size) {
    const float* verts = (const float*)d_in[0];
    const int*   edges = (const int*)  d_in[1];   // int32
    const float* w0a = (const float*)d_in[2];
    const float* b0a = (const float*)d_in[3];
    const float* w1a = (const float*)d_in[4];
    const float* b1a = (const float*)d_in[5];
    const float* w0b = (const float*)d_in[6];
    const float* b0b = (const float*)d_in[7];
    const float* w1b = (const float*)d_in[8];
    const float* b1b = (const float*)d_in[9];
    const float* fc1_w = (const float*)d_in[10];
    const float* fc1_b = (const float*)d_in[11];
    const float* fc2_w = (const float*)d_in[12];
    const float* fc2_b = (const float*)d_in[13];
    float* out = (float*)d_out;

    const int eblocks = NE / 256;        // 17550, exact
    const int vblocks = NV / 256;        // 5850, exact

    k0_pad      <<<NV/4/128, 128>>>(verts, fc2_w);   // 2925 blocks, exact
    k1_edge_agg1<<<eblocks, 256>>>(edges);
    k2_vert1    <<<NV/2/256, 256>>>(w0a, b0a, w1a, b1a);  // 2925 blocks, exact
    k3_edge_agg2<<<eblocks, 256>>>(edges);
    k4_vert2_fc1<<<vblocks, 256>>>(w0b, b0b, w1b, b1b, fc1_w, fc1_b);
    dim3 g5(K5_GRIDX, 2);
    k5_fc2      <<<g5, 256>>>();
    k6_softmax  <<<BATCH, 64>>>(fc2_b, out);
}